// round 10
// baseline (speedup 1.0000x reference)
#include <cuda_runtime.h>
#include <cuda_fp16.h>
#include <math.h>
#include <cstdint>

// Problem constants
#define BATCH   2048
#define LAT     256
#define HID     1024
#define OUTD    512
#define TSTEPS  100
#define NSUB    10
#define NCTA    128
#define NTHR    256
#define NGRP    16          // independent batch groups
#define GSZ     8           // CTAs per group

enum { MODE_ELU = 0, MODE_EULER = 1, MODE_PLAIN = 2 };

// ---------------------------------------------------------------------------
// Device scratch (no cudaMalloc allowed)
// ---------------------------------------------------------------------------
__device__ __align__(256) float g_zs[(size_t)TSTEPS * BATCH * LAT];
__device__ __align__(256) float g_h1[(size_t)BATCH * HID];
__device__ __align__(256) float g_h2[(size_t)BATCH * HID];
__device__ __align__(256) float g_za[(size_t)BATCH * LAT];
__device__ __align__(256) float g_zb[(size_t)BATCH * LAT];
__device__ __align__(256) float g_Md[(size_t)OUTD * LAT];
__device__ __align__(256) float g_cd[OUTD];

// Pre-split weights: fp16 hi/lo (hi = rn(x), lo = rn(x - hi))
__device__ __align__(256) __half g_w1h[(size_t)HID * LAT],  g_w1l[(size_t)HID * LAT];
__device__ __align__(256) __half g_w2h[(size_t)HID * HID],  g_w2l[(size_t)HID * HID];
__device__ __align__(256) __half g_w3h[(size_t)LAT * HID],  g_w3l[(size_t)LAT * HID];
__device__ __align__(256) __half g_Mdh[(size_t)OUTD * LAT], g_Mdl[(size_t)OUTD * LAT];

// Per-group barrier state: one 128B line per group (32 u32). Returns to 0
// every launch (even #barriers per group, counters self-reset).
__device__ __align__(256) unsigned g_gcnt[NGRP * 32];
__device__ __align__(256) unsigned g_gsense[NGRP * 32];

// Smem: 2 buffers x 4 tiles (Ah,Al,Bh,Bl); tile = 128 rows x 36 half2
// (payload now 32 half2 = 64 halves = one K64 chunk; stride 36 keeps the
// proven conflict-free pattern for 16B STS, cp.async, and scalar frag LDS).
#define SA       36                    // half2 per row
#define TILE_H   (128 * SA)            // half2 per tile
#define BUF_H    (4 * TILE_H)          // half2 per buffer
#define TILE_B   (TILE_H * 4)          // bytes per tile
#define SMEM_BYTES (2 * BUF_H * 4)     // 147456 B

// ---------------------------------------------------------------------------
// Helpers
// ---------------------------------------------------------------------------
__device__ __forceinline__ uint32_t smem_u32(const void* p) {
    uint32_t a;
    asm("{ .reg .u64 t; cvta.to.shared.u64 t, %1; cvt.u32.u64 %0, t; }" : "=r"(a) : "l"(p));
    return a;
}

__device__ __forceinline__ void cp16(uint32_t dst, const void* src) {
    asm volatile("cp.async.cg.shared.global [%0], [%1], 16;" :: "r"(dst), "l"(src));
}
#define CP_COMMIT() asm volatile("cp.async.commit_group;" ::: "memory")
#define CP_WAIT0()  asm volatile("cp.async.wait_group 0;" ::: "memory")

// D += A*B (m16n8k16 fp16 inputs, fp32 accumulate)
__device__ __forceinline__ void mma16(float (&d)[4],
                                      uint32_t a0, uint32_t a1, uint32_t a2, uint32_t a3,
                                      uint32_t b0, uint32_t b1) {
    asm volatile(
        "mma.sync.aligned.m16n8k16.row.col.f32.f16.f16.f32 "
        "{%0,%1,%2,%3}, {%4,%5,%6,%7}, {%8,%9}, {%0,%1,%2,%3};"
        : "+f"(d[0]), "+f"(d[1]), "+f"(d[2]), "+f"(d[3])
        : "r"(a0), "r"(a1), "r"(a2), "r"(a3), "r"(b0), "r"(b1));
}

// split 2 floats into hi/lo packed half2 bit patterns (x -> low 16 bits)
__device__ __forceinline__ void split2(float x, float y, uint32_t& hi, uint32_t& lo) {
    __half hx = __float2half_rn(x), hy = __float2half_rn(y);
    __half lx = __float2half_rn(x - __half2float(hx));
    __half ly = __float2half_rn(y - __half2float(hy));
    hi = (uint32_t)__half_as_ushort(hx) | ((uint32_t)__half_as_ushort(hy) << 16);
    lo = (uint32_t)__half_as_ushort(lx) | ((uint32_t)__half_as_ushort(ly) << 16);
}

// ---------------------------------------------------------------------------
// Group barrier: 8 arrivals, release/acquire at gpu scope, per-group lines.
// ---------------------------------------------------------------------------
__device__ __forceinline__ void group_sync(unsigned* s_sense, int grp) {
    __syncthreads();
    if (threadIdx.x == 0) {
        unsigned* cnt = &g_gcnt[grp * 32];
        unsigned* sen = &g_gsense[grp * 32];
        unsigned my = *s_sense ^ 1u;
        *s_sense = my;
        unsigned old;
        asm volatile("atom.release.gpu.global.add.u32 %0, [%1], %2;"
                     : "=r"(old) : "l"(cnt), "r"(1u) : "memory");
        if (old == GSZ - 1u) {
            asm volatile("st.relaxed.gpu.global.u32 [%0], %1;" :: "l"(cnt), "r"(0u) : "memory");
            asm volatile("st.release.gpu.global.u32 [%0], %1;" :: "l"(sen), "r"(my) : "memory");
        } else {
            unsigned cur;
            do {
                asm volatile("ld.acquire.gpu.global.u32 %0, [%1];"
                             : "=r"(cur) : "l"(sen) : "memory");
            } while (cur != my);
        }
    }
    __syncthreads();
}

// ---------------------------------------------------------------------------
// One BM x BN output tile:  C[m,n] = epilogue( sum_k A[m,k]*W[n,k] + bias[n] )
// 3-term fp16 split (AhBh + AhBl + AlBh), fp32 register accumulators.
// 256 threads = 8 warps (2x4). K chunks of 64. Double-buffered smem;
// A split on the fly; B streamed via cp.async from pre-split fp16 weights.
// ---------------------------------------------------------------------------
template <int BM, int BN, int MODE>
__device__ __forceinline__ void tile_mma(
    const float* __restrict__ A,
    const __half* __restrict__ Wh, const __half* __restrict__ Wl,
    const float* __restrict__ bias, const float* __restrict__ Zp,
    float* __restrict__ C, int N, int K, float h,
    int mB, int nB, __half2* sm, uint32_t smb) {

    constexpr int MT = BM / 32;        // mma tiles per warp (M): 4 or 2
    constexpr int NT = BN / 32;        // mma tiles per warp (N): 4 or 2
    constexpr int WM = MT * 16;
    constexpr int WN = NT * 8;
    constexpr int AG = BM / 64;        // 16-float A groups per thread (2 or 1)
    constexpr int BG = BN / 32;        // cp16 per thread per B matrix (4 or 2)

    const int tid  = threadIdx.x;
    const int lane = tid & 31;
    const int warp = tid >> 5;
    const int wmi  = warp >> 2;        // 0..1
    const int wni  = warp & 3;         // 0..3
    const int nTc  = K >> 6;           // 64-float K chunks

    float4 ra[AG][4];
    float acc[MT][NT][4];
#pragma unroll
    for (int i = 0; i < MT; i++)
#pragma unroll
        for (int j = 0; j < NT; j++)
#pragma unroll
            for (int c = 0; c < 4; c++) acc[i][j][c] = 0.0f;

    auto ldgA = [&](int t) {
#pragma unroll
        for (int i = 0; i < AG; i++) {
            int idx = tid + i * NTHR, row = idx >> 2, g = idx & 3;
            const float* p = A + (size_t)(mB + row) * K + t * 64 + g * 16;
            ra[i][0] = __ldcg((const float4*)p);
            ra[i][1] = __ldcg((const float4*)(p + 4));
            ra[i][2] = __ldcg((const float4*)(p + 8));
            ra[i][3] = __ldcg((const float4*)(p + 12));
        }
    };
    auto cpB = [&](int t, int b) {
        const uint32_t base = smb + (uint32_t)b * (BUF_H * 4) + 2 * TILE_B;
#pragma unroll
        for (int i = 0; i < BG; i++) {
            int idx = tid + i * NTHR, row = idx >> 3, c = idx & 7;
            const size_t o = (size_t)(nB + row) * K + t * 64 + c * 8;
            const uint32_t d = base + (uint32_t)(row * SA + c * 4) * 4;
            cp16(d, Wh + o);
            cp16(d + TILE_B, Wl + o);
        }
        CP_COMMIT();
    };
    auto stsA = [&](int b) {
        __half2* sAh = sm + b * BUF_H;
        __half2* sAl = sAh + TILE_H;
#pragma unroll
        for (int i = 0; i < AG; i++) {
            int idx = tid + i * NTHR, row = idx >> 2, g = idx & 3;
            uint4 h0, l0, h1, l1;
            split2(ra[i][0].x, ra[i][0].y, h0.x, l0.x);
            split2(ra[i][0].z, ra[i][0].w, h0.y, l0.y);
            split2(ra[i][1].x, ra[i][1].y, h0.z, l0.z);
            split2(ra[i][1].z, ra[i][1].w, h0.w, l0.w);
            split2(ra[i][2].x, ra[i][2].y, h1.x, l1.x);
            split2(ra[i][2].z, ra[i][2].w, h1.y, l1.y);
            split2(ra[i][3].x, ra[i][3].y, h1.z, l1.z);
            split2(ra[i][3].z, ra[i][3].w, h1.w, l1.w);
            const int p = row * SA + g * 8;
            *(uint4*)(sAh + p)     = h0;
            *(uint4*)(sAh + p + 4) = h1;
            *(uint4*)(sAl + p)     = l0;
            *(uint4*)(sAl + p + 4) = l1;
        }
    };

    // prologue: fill buffer 0
    ldgA(0);
    cpB(0, 0);
    stsA(0);
    CP_WAIT0();
    __syncthreads();

    const int rA = wmi * WM + (lane >> 2);
    const int rB = wni * WN + (lane >> 2);
    const int cK = lane & 3;           // half2 index within 8-half2 k16 block

    for (int t = 0; t < nTc; ++t) {
        const int cur = t & 1, nxt = cur ^ 1;
        if (t + 1 < nTc) {
            ldgA(t + 1);
            cpB(t + 1, nxt);
        }

        const uint32_t* sAh = (const uint32_t*)(sm + cur * BUF_H);
        const uint32_t* sAl = sAh + TILE_H;
        const uint32_t* sBh = sAl + TILE_H;
        const uint32_t* sBl = sBh + TILE_H;

#pragma unroll
        for (int blk = 0; blk < 4; blk++) {          // four k16 blocks per chunk
            const int kb = blk * 8 + cK;
            uint32_t ah[MT][4], al[MT][4], bh[NT][2], bl[NT][2];
#pragma unroll
            for (int i = 0; i < MT; i++) {
                const int r0 = (rA + i * 16) * SA, r1 = r0 + 8 * SA;
                ah[i][0] = sAh[r0 + kb];
                ah[i][1] = sAh[r1 + kb];
                ah[i][2] = sAh[r0 + kb + 4];
                ah[i][3] = sAh[r1 + kb + 4];
                al[i][0] = sAl[r0 + kb];
                al[i][1] = sAl[r1 + kb];
                al[i][2] = sAl[r0 + kb + 4];
                al[i][3] = sAl[r1 + kb + 4];
            }
#pragma unroll
            for (int j = 0; j < NT; j++) {
                const int rn = (rB + j * 8) * SA;
                bh[j][0] = sBh[rn + kb];
                bh[j][1] = sBh[rn + kb + 4];
                bl[j][0] = sBl[rn + kb];
                bl[j][1] = sBl[rn + kb + 4];
            }
#pragma unroll
            for (int i = 0; i < MT; i++)
#pragma unroll
                for (int j = 0; j < NT; j++) {
                    mma16(acc[i][j], ah[i][0], ah[i][1], ah[i][2], ah[i][3], bh[j][0], bh[j][1]);
                    mma16(acc[i][j], ah[i][0], ah[i][1], ah[i][2], ah[i][3], bl[j][0], bl[j][1]);
                    mma16(acc[i][j], al[i][0], al[i][1], al[i][2], al[i][3], bh[j][0], bh[j][1]);
                }
        }

        if (t + 1 < nTc) {
            stsA(nxt);
            CP_WAIT0();
            __syncthreads();
        }
    }

    // ---- epilogue: bias + mode, float2 stores straight from accumulators ----
#pragma unroll
    for (int i = 0; i < MT; i++) {
        const int gm0 = mB + wmi * WM + i * 16 + (lane >> 2);
#pragma unroll
        for (int j = 0; j < NT; j++) {
            const int gn = nB + wni * WN + j * 8 + (lane & 3) * 2;
            const float bi0 = __ldg(bias + gn), bi1 = __ldg(bias + gn + 1);
            float x0 = acc[i][j][0] + bi0, x1 = acc[i][j][1] + bi1;
            float x2 = acc[i][j][2] + bi0, x3 = acc[i][j][3] + bi1;
            if (MODE == MODE_ELU) {
                x0 = x0 > 0.0f ? x0 : expm1f(x0);
                x1 = x1 > 0.0f ? x1 : expm1f(x1);
                x2 = x2 > 0.0f ? x2 : expm1f(x2);
                x3 = x3 > 0.0f ? x3 : expm1f(x3);
            }
            const size_t g0 = (size_t)gm0 * N + gn;
            const size_t g1 = (size_t)(gm0 + 8) * N + gn;
            if (MODE == MODE_EULER) {
                float2 z0v = __ldcg((const float2*)(Zp + g0));
                float2 z1v = __ldcg((const float2*)(Zp + g1));
                x0 = z0v.x + h * x0; x1 = z0v.y + h * x1;
                x2 = z1v.x + h * x2; x3 = z1v.y + h * x3;
            }
            *(float2*)(C + g0) = make_float2(x0, x1);
            *(float2*)(C + g1) = make_float2(x2, x3);
        }
    }
}

// ---------------------------------------------------------------------------
// Persistent ODE integrator: 16 independent groups of 8 CTAs; group g owns
// batch rows [128g, 128g+128). Barriers are group-scoped (8 arrivals).
// Per-group barriers: 1 + 99*10*3 + 1 = 2972 (even -> sense ends at 0).
// ---------------------------------------------------------------------------
__global__ void __launch_bounds__(NTHR, 1)
ode_persistent(const float* __restrict__ z0, const float* __restrict__ tv,
               const float* __restrict__ b1, const float* __restrict__ b2,
               const float* __restrict__ b3,
               float* __restrict__ zs, float* __restrict__ h1,
               float* __restrict__ h2, float* __restrict__ za,
               float* __restrict__ zb) {
    extern __shared__ __half2 sm[];
    const uint32_t smb = smem_u32(sm);
    __shared__ unsigned s_sense;
    if (threadIdx.x == 0) s_sense = 0u;

    const int bx  = blockIdx.x;
    const int grp = bx >> 3;           // 0..15
    const int l   = bx & 7;            // 0..7

    // zs[0] rows for this group: CTA copies its 16 rows (16*256 floats)
    {
        const int rowBase = grp * 128 + l * 16;
        const float4* src = (const float4*)z0 + (size_t)rowBase * (LAT / 4);
        float4*       dst = (float4*)zs + (size_t)rowBase * (LAT / 4);
        for (int i = threadIdx.x; i < 16 * (LAT / 4); i += NTHR)
            dst[i] = __ldcg(src + i);
    }
    group_sync(&s_sense, grp);                              // barrier 1

    const int mB1 = grp * 128,            nB1 = l * 128;            // G1/G2
    const int mB3 = grp * 128 + (l >> 2) * 64, nB3 = (l & 3) * 64;  // G3
    const size_t BL = (size_t)BATCH * LAT;

    for (int it = 0; it < TSTEPS - 1; ++it) {
        const float hstep = (__ldg(tv + it + 1) - __ldg(tv + it)) * (1.0f / NSUB);
        for (int s = 0; s < NSUB; s++) {
            const float* zin  = (s == 0)        ? zs + (size_t)it * BL
                                                : ((s & 1) ? za : zb);
            float*       zout = (s == NSUB - 1) ? zs + (size_t)(it + 1) * BL
                                                : ((s & 1) ? zb : za);
            // h1 = elu(z @ w1.T + b1)   [rows of group, K=256]
            tile_mma<128, 128, MODE_ELU>(zin, g_w1h, g_w1l, b1, nullptr, h1,
                                         HID, LAT, 0.f, mB1, nB1, sm, smb);
            group_sync(&s_sense, grp);
            // h2 = elu(h1 @ w2.T + b2)  [K=1024]
            tile_mma<128, 128, MODE_ELU>(h1, g_w2h, g_w2l, b2, nullptr, h2,
                                         HID, HID, 0.f, mB1, nB1, sm, smb);
            group_sync(&s_sense, grp);
            // zout = zin + h*(h2 @ w3.T + b3)  [K=1024]
            tile_mma<64, 64, MODE_EULER>(h2, g_w3h, g_w3l, b3, zin, zout,
                                         LAT, HID, hstep, mB3, nB3, sm, smb);
            group_sync(&s_sense, grp);
        }
    }
    group_sync(&s_sense, grp);   // pad -> even count (2972)
}

// ---------------------------------------------------------------------------
// Folded decoder: out = zs @ Md.T + cd   (M=204800, N=512, K=256)
// ---------------------------------------------------------------------------
__global__ void __launch_bounds__(NTHR, 1)
decoder_gemm(const float* __restrict__ zs, const float* __restrict__ cd,
             float* __restrict__ out) {
    extern __shared__ __half2 sm[];
    const uint32_t smb = smem_u32(sm);
    tile_mma<128, 128, MODE_PLAIN>(zs, g_Mdh, g_Mdl, cd, nullptr, out,
                                   OUTD, LAT, 0.f,
                                   blockIdx.y * 128, blockIdx.x * 128, sm, smb);
}

// ---------------------------------------------------------------------------
// Prep: decoder fold + fp16 hi/lo weight splits (tiny, once per launch)
// ---------------------------------------------------------------------------
__global__ void combine_kernel(const float* __restrict__ h2o_w,
                               const float* __restrict__ l2h_w,
                               float* __restrict__ Md) {
    __shared__ float sW[16][17];
    __shared__ float sL[16][17];
    const int o = blockIdx.y * 16 + threadIdx.y;
    const int l = blockIdx.x * 16 + threadIdx.x;
    float acc = 0.0f;
    for (int h0 = 0; h0 < HID; h0 += 16) {
        sW[threadIdx.y][threadIdx.x] = h2o_w[(size_t)o * HID + h0 + threadIdx.x];
        sL[threadIdx.y][threadIdx.x] = l2h_w[(size_t)(h0 + threadIdx.y) * LAT + l];
        __syncthreads();
#pragma unroll
        for (int kk = 0; kk < 16; kk++) acc += sW[threadIdx.y][kk] * sL[kk][threadIdx.x];
        __syncthreads();
    }
    Md[(size_t)o * LAT + l] = acc;
}

__global__ void cvec_kernel(const float* __restrict__ h2o_w,
                            const float* __restrict__ l2h_b,
                            const float* __restrict__ h2o_b,
                            float* __restrict__ cd) {
    const int o = blockIdx.x * blockDim.x + threadIdx.x;
    if (o < OUTD) {
        float a = h2o_b[o];
        for (int h = 0; h < HID; h++) a += h2o_w[(size_t)o * HID + h] * l2h_b[h];
        cd[o] = a;
    }
}

__global__ void split_kernel(const float* __restrict__ w,
                             __half* __restrict__ wh, __half* __restrict__ wl, int n) {
    const int i = blockIdx.x * blockDim.x + threadIdx.x;
    if (i < n) {
        float x = w[i];
        __half hi = __float2half_rn(x);
        wh[i] = hi;
        wl[i] = __float2half_rn(x - __half2float(hi));
    }
}

// ---------------------------------------------------------------------------
// Graph nodes: combine, cvec, 4x split, persistent ODE, decoder.
// ---------------------------------------------------------------------------
extern "C" void kernel_launch(void* const* d_in, const int* in_sizes, int n_in,
                              void* d_out, int out_size) {
    const float* z0    = (const float*)d_in[0];
    const float* tv    = (const float*)d_in[1];
    const float* w1    = (const float*)d_in[2];
    const float* b1    = (const float*)d_in[3];
    const float* w2    = (const float*)d_in[4];
    const float* b2    = (const float*)d_in[5];
    const float* w3    = (const float*)d_in[6];
    const float* b3    = (const float*)d_in[7];
    const float* l2h_w = (const float*)d_in[8];
    const float* l2h_b = (const float*)d_in[9];
    const float* h2o_w = (const float*)d_in[10];
    const float* h2o_b = (const float*)d_in[11];
    float* out = (float*)d_out;

    float *zs, *h1, *h2, *za, *zb, *Md, *cd;
    __half *w1h, *w1l, *w2h, *w2l, *w3h, *w3l, *Mdh, *Mdl;
    cudaGetSymbolAddress((void**)&zs, g_zs);
    cudaGetSymbolAddress((void**)&h1, g_h1);
    cudaGetSymbolAddress((void**)&h2, g_h2);
    cudaGetSymbolAddress((void**)&za, g_za);
    cudaGetSymbolAddress((void**)&zb, g_zb);
    cudaGetSymbolAddress((void**)&Md, g_Md);
    cudaGetSymbolAddress((void**)&cd, g_cd);
    cudaGetSymbolAddress((void**)&w1h, g_w1h);
    cudaGetSymbolAddress((void**)&w1l, g_w1l);
    cudaGetSymbolAddress((void**)&w2h, g_w2h);
    cudaGetSymbolAddress((void**)&w2l, g_w2l);
    cudaGetSymbolAddress((void**)&w3h, g_w3h);
    cudaGetSymbolAddress((void**)&w3l, g_w3l);
    cudaGetSymbolAddress((void**)&Mdh, g_Mdh);
    cudaGetSymbolAddress((void**)&Mdl, g_Mdl);

    static bool attr_done = false;
    if (!attr_done) {
        cudaFuncSetAttribute(ode_persistent,
                             cudaFuncAttributeMaxDynamicSharedMemorySize, SMEM_BYTES);
        cudaFuncSetAttribute(decoder_gemm,
                             cudaFuncAttributeMaxDynamicSharedMemorySize, SMEM_BYTES);
        attr_done = true;
    }

    // prep: decoder fold + weight splits
    combine_kernel<<<dim3(LAT / 16, OUTD / 16), dim3(16, 16)>>>(h2o_w, l2h_w, Md);
    cvec_kernel<<<2, 256>>>(h2o_w, l2h_b, h2o_b, cd);
    split_kernel<<<(HID * LAT + 255) / 256, 256>>>(w1, w1h, w1l, HID * LAT);
    split_kernel<<<(HID * HID + 255) / 256, 256>>>(w2, w2h, w2l, HID * HID);
    split_kernel<<<(LAT * HID + 255) / 256, 256>>>(w3, w3h, w3l, LAT * HID);
    split_kernel<<<(OUTD * LAT + 255) / 256, 256>>>(Md, Mdh, Mdl, OUTD * LAT);

    ode_persistent<<<NCTA, NTHR, SMEM_BYTES>>>(z0, tv, b1, b2, b3,
                                               zs, h1, h2, za, zb);

    decoder_gemm<<<dim3(OUTD / 128, TSTEPS * BATCH / 128), NTHR, SMEM_BYTES>>>(zs, cd, out);
}

// round 11
// speedup vs baseline: 1.0141x; 1.0141x over previous
#include <cuda_runtime.h>
#include <cuda_fp16.h>
#include <math.h>
#include <cstdint>

// Problem constants
#define BATCH   2048
#define LAT     256
#define HID     1024
#define OUTD    512
#define TSTEPS  100
#define NSUB    10
#define NCTA    128
#define NTHR    256
#define NGRP    16          // independent batch groups
#define GSZ     8           // CTAs per group

enum { MODE_ELU = 0, MODE_EULER = 1, MODE_PLAIN = 2 };

// ---------------------------------------------------------------------------
// Device scratch (no cudaMalloc allowed)
// ---------------------------------------------------------------------------
__device__ __align__(256) float g_zs[(size_t)TSTEPS * BATCH * LAT];
__device__ __align__(256) float g_h1[(size_t)BATCH * HID];
__device__ __align__(256) float g_h2[(size_t)BATCH * HID];
__device__ __align__(256) float g_za[(size_t)BATCH * LAT];
__device__ __align__(256) float g_zb[(size_t)BATCH * LAT];
__device__ __align__(256) float g_Md[(size_t)OUTD * LAT];
__device__ __align__(256) float g_cd[OUTD];

// Pre-split weights: fp16 hi/lo (hi = rn(x), lo = rn(x - hi))
__device__ __align__(256) __half g_w1h[(size_t)HID * LAT],  g_w1l[(size_t)HID * LAT];
__device__ __align__(256) __half g_w2h[(size_t)HID * HID],  g_w2l[(size_t)HID * HID];
__device__ __align__(256) __half g_w3h[(size_t)LAT * HID],  g_w3l[(size_t)LAT * HID];
__device__ __align__(256) __half g_Mdh[(size_t)OUTD * LAT], g_Mdl[(size_t)OUTD * LAT];

// Per-group barrier state: one 128B line per group. Returns to 0 every launch
// (even #barriers per group, counters self-reset).
__device__ __align__(256) unsigned g_gcnt[NGRP * 32];
__device__ __align__(256) unsigned g_gsense[NGRP * 32];

// Smem: 2 buffers x 4 tiles (Ah,Al,Bh,Bl); tile = 128 rows x 36 half2
// (stride 36: proven conflict-free for 16B STS, cp.async, scalar frag LDS).
#define SA       36                    // half2 per row
#define TILE_H   (128 * SA)            // half2 per tile
#define BUF_H    (4 * TILE_H)          // half2 per buffer
#define TILE_B   (TILE_H * 4)          // bytes per tile
#define SMEM_BYTES (2 * BUF_H * 4)     // 147456 B

// ---------------------------------------------------------------------------
// Helpers
// ---------------------------------------------------------------------------
__device__ __forceinline__ uint32_t smem_u32(const void* p) {
    uint32_t a;
    asm("{ .reg .u64 t; cvta.to.shared.u64 t, %1; cvt.u32.u64 %0, t; }" : "=r"(a) : "l"(p));
    return a;
}

__device__ __forceinline__ void cp16(uint32_t dst, const void* src) {
    asm volatile("cp.async.cg.shared.global [%0], [%1], 16;" :: "r"(dst), "l"(src));
}
#define CP_COMMIT() asm volatile("cp.async.commit_group;" ::: "memory")
#define CP_WAIT0()  asm volatile("cp.async.wait_group 0;" ::: "memory")

// D += A*B (m16n8k16 fp16 inputs, fp32 accumulate)
__device__ __forceinline__ void mma16(float (&d)[4],
                                      uint32_t a0, uint32_t a1, uint32_t a2, uint32_t a3,
                                      uint32_t b0, uint32_t b1) {
    asm volatile(
        "mma.sync.aligned.m16n8k16.row.col.f32.f16.f16.f32 "
        "{%0,%1,%2,%3}, {%4,%5,%6,%7}, {%8,%9}, {%0,%1,%2,%3};"
        : "+f"(d[0]), "+f"(d[1]), "+f"(d[2]), "+f"(d[3])
        : "r"(a0), "r"(a1), "r"(a2), "r"(a3), "r"(b0), "r"(b1));
}

// split 2 floats into hi/lo packed half2 bit patterns (x -> low 16 bits)
__device__ __forceinline__ void split2(float x, float y, uint32_t& hi, uint32_t& lo) {
    __half hx = __float2half_rn(x), hy = __float2half_rn(y);
    __half lx = __float2half_rn(x - __half2float(hx));
    __half ly = __float2half_rn(y - __half2float(hy));
    hi = (uint32_t)__half_as_ushort(hx) | ((uint32_t)__half_as_ushort(hy) << 16);
    lo = (uint32_t)__half_as_ushort(lx) | ((uint32_t)__half_as_ushort(ly) << 16);
}

// ---------------------------------------------------------------------------
// Group barrier: 8 arrivals, release/acquire at gpu scope, per-group lines.
// ---------------------------------------------------------------------------
__device__ __forceinline__ void group_sync(unsigned* s_sense, int grp) {
    __syncthreads();
    if (threadIdx.x == 0) {
        unsigned* cnt = &g_gcnt[grp * 32];
        unsigned* sen = &g_gsense[grp * 32];
        unsigned my = *s_sense ^ 1u;
        *s_sense = my;
        unsigned old;
        asm volatile("atom.release.gpu.global.add.u32 %0, [%1], %2;"
                     : "=r"(old) : "l"(cnt), "r"(1u) : "memory");
        if (old == GSZ - 1u) {
            asm volatile("st.relaxed.gpu.global.u32 [%0], %1;" :: "l"(cnt), "r"(0u) : "memory");
            asm volatile("st.release.gpu.global.u32 [%0], %1;" :: "l"(sen), "r"(my) : "memory");
        } else {
            unsigned cur;
            do {
                asm volatile("ld.acquire.gpu.global.u32 %0, [%1];"
                             : "=r"(cur) : "l"(sen) : "memory");
            } while (cur != my);
        }
    }
    __syncthreads();
}

// ---------------------------------------------------------------------------
// One BM x BN output tile:  C[m,n] = epilogue( sum_k A[m,k]*W[n,k] + bias[n] )
// 3-term fp16 split (AhBh + AhBl + AlBh), fp32 register accumulators.
// TERM-MAJOR mma ordering: all hh, then all hl, then all lh — RAW distance
// per accumulator = MT*NT instructions instead of 1 (kills accumulate-chain
// stalls); per-accumulator addition order unchanged -> bit-identical result.
// 256 threads = 8 warps (2x4). K chunks of 32 (R9-proven). Double-buffered;
// A split on the fly; B streamed via cp.async from pre-split fp16 weights.
// ---------------------------------------------------------------------------
template <int BM, int BN, int MODE>
__device__ __forceinline__ void tile_mma(
    const float* __restrict__ A,
    const __half* __restrict__ Wh, const __half* __restrict__ Wl,
    const float* __restrict__ bias, const float* __restrict__ Zp,
    float* __restrict__ C, int N, int K, float h,
    int mB, int nB, __half2* sm, uint32_t smb) {

    constexpr int MT = BM / 32;        // mma tiles per warp (M): 4 or 2
    constexpr int NT = BN / 32;        // mma tiles per warp (N): 4 or 2
    constexpr int WM = MT * 16;
    constexpr int WN = NT * 8;
    constexpr int AG = BM * 4 / NTHR;  // A 8-float groups per thread
    constexpr int BG = BN * 4 / NTHR;  // B 16B cp groups per thread

    const int tid  = threadIdx.x;
    const int lane = tid & 31;
    const int warp = tid >> 5;
    const int wmi  = warp >> 2;        // 0..1
    const int wni  = warp & 3;         // 0..3
    const int nTc  = K >> 5;

    float4 ra[AG][2];
    float acc[MT][NT][4];
#pragma unroll
    for (int i = 0; i < MT; i++)
#pragma unroll
        for (int j = 0; j < NT; j++)
#pragma unroll
            for (int c = 0; c < 4; c++) acc[i][j][c] = 0.0f;

    auto ldgA = [&](int t) {
#pragma unroll
        for (int i = 0; i < AG; i++) {
            int idx = tid + i * NTHR, row = idx >> 2, g = idx & 3;
            const float* p = A + (size_t)(mB + row) * K + t * 32 + g * 8;
            ra[i][0] = __ldcg((const float4*)p);
            ra[i][1] = __ldcg((const float4*)(p + 4));
        }
    };
    auto cpB = [&](int t, int b) {
        const uint32_t base = smb + (uint32_t)b * (BUF_H * 4) + 2 * TILE_B;
#pragma unroll
        for (int i = 0; i < BG; i++) {
            int idx = tid + i * NTHR, row = idx >> 2, c = idx & 3;
            const size_t o = (size_t)(nB + row) * K + t * 32 + c * 8;
            const uint32_t d = base + (uint32_t)(row * SA + c * 4) * 4;
            cp16(d, Wh + o);
            cp16(d + TILE_B, Wl + o);
        }
        CP_COMMIT();
    };
    auto stsA = [&](int b) {
        __half2* sAh = sm + b * BUF_H;
        __half2* sAl = sAh + TILE_H;
#pragma unroll
        for (int i = 0; i < AG; i++) {
            int idx = tid + i * NTHR, row = idx >> 2, g = idx & 3;
            uint4 hi, lo;
            split2(ra[i][0].x, ra[i][0].y, hi.x, lo.x);
            split2(ra[i][0].z, ra[i][0].w, hi.y, lo.y);
            split2(ra[i][1].x, ra[i][1].y, hi.z, lo.z);
            split2(ra[i][1].z, ra[i][1].w, hi.w, lo.w);
            const int p = row * SA + g * 4;
            *(uint4*)(sAh + p) = hi;
            *(uint4*)(sAl + p) = lo;
        }
    };

    // prologue: fill buffer 0
    ldgA(0);
    cpB(0, 0);
    stsA(0);
    CP_WAIT0();
    __syncthreads();

    const int rA = wmi * WM + (lane >> 2);
    const int rB = wni * WN + (lane >> 2);
    const int cK = lane & 3;           // half2 index within 8-half2 k16 block

    for (int t = 0; t < nTc; ++t) {
        const int cur = t & 1, nxt = cur ^ 1;
        if (t + 1 < nTc) {
            ldgA(t + 1);
            cpB(t + 1, nxt);
        }

        const uint32_t* sAh = (const uint32_t*)(sm + cur * BUF_H);
        const uint32_t* sAl = sAh + TILE_H;
        const uint32_t* sBh = sAl + TILE_H;
        const uint32_t* sBl = sBh + TILE_H;

#pragma unroll
        for (int blk = 0; blk < 2; blk++) {          // two k16 blocks per chunk
            const int kb = blk * 8 + cK;
            uint32_t ah[MT][4], al[MT][4], bh[NT][2], bl[NT][2];
#pragma unroll
            for (int i = 0; i < MT; i++) {
                const int r0 = (rA + i * 16) * SA, r1 = r0 + 8 * SA;
                ah[i][0] = sAh[r0 + kb];
                ah[i][1] = sAh[r1 + kb];
                ah[i][2] = sAh[r0 + kb + 4];
                ah[i][3] = sAh[r1 + kb + 4];
                al[i][0] = sAl[r0 + kb];
                al[i][1] = sAl[r1 + kb];
                al[i][2] = sAl[r0 + kb + 4];
                al[i][3] = sAl[r1 + kb + 4];
            }
#pragma unroll
            for (int j = 0; j < NT; j++) {
                const int rn = (rB + j * 8) * SA;
                bh[j][0] = sBh[rn + kb];
                bh[j][1] = sBh[rn + kb + 4];
                bl[j][0] = sBl[rn + kb];
                bl[j][1] = sBl[rn + kb + 4];
            }
            // term-major: MT*NT independent mmas between reuses of any acc
#pragma unroll
            for (int i = 0; i < MT; i++)
#pragma unroll
                for (int j = 0; j < NT; j++)
                    mma16(acc[i][j], ah[i][0], ah[i][1], ah[i][2], ah[i][3], bh[j][0], bh[j][1]);
#pragma unroll
            for (int i = 0; i < MT; i++)
#pragma unroll
                for (int j = 0; j < NT; j++)
                    mma16(acc[i][j], ah[i][0], ah[i][1], ah[i][2], ah[i][3], bl[j][0], bl[j][1]);
#pragma unroll
            for (int i = 0; i < MT; i++)
#pragma unroll
                for (int j = 0; j < NT; j++)
                    mma16(acc[i][j], al[i][0], al[i][1], al[i][2], al[i][3], bh[j][0], bh[j][1]);
        }

        if (t + 1 < nTc) {
            stsA(nxt);
            CP_WAIT0();
            __syncthreads();
        }
    }

    // ---- epilogue: bias + mode, float2 stores straight from accumulators ----
#pragma unroll
    for (int i = 0; i < MT; i++) {
        const int gm0 = mB + wmi * WM + i * 16 + (lane >> 2);
#pragma unroll
        for (int j = 0; j < NT; j++) {
            const int gn = nB + wni * WN + j * 8 + (lane & 3) * 2;
            const float bi0 = __ldg(bias + gn), bi1 = __ldg(bias + gn + 1);
            float x0 = acc[i][j][0] + bi0, x1 = acc[i][j][1] + bi1;
            float x2 = acc[i][j][2] + bi0, x3 = acc[i][j][3] + bi1;
            if (MODE == MODE_ELU) {
                x0 = x0 > 0.0f ? x0 : expm1f(x0);
                x1 = x1 > 0.0f ? x1 : expm1f(x1);
                x2 = x2 > 0.0f ? x2 : expm1f(x2);
                x3 = x3 > 0.0f ? x3 : expm1f(x3);
            }
            const size_t g0 = (size_t)gm0 * N + gn;
            const size_t g1 = (size_t)(gm0 + 8) * N + gn;
            if (MODE == MODE_EULER) {
                float2 z0v = __ldcg((const float2*)(Zp + g0));
                float2 z1v = __ldcg((const float2*)(Zp + g1));
                x0 = z0v.x + h * x0; x1 = z0v.y + h * x1;
                x2 = z1v.x + h * x2; x3 = z1v.y + h * x3;
            }
            *(float2*)(C + g0) = make_float2(x0, x1);
            *(float2*)(C + g1) = make_float2(x2, x3);
        }
    }
}

// ---------------------------------------------------------------------------
// Persistent ODE integrator: 16 independent groups of 8 CTAs; group g owns
// batch rows [128g, 128g+128). Barriers are group-scoped (8 arrivals).
// Per-group barriers: 1 + 99*10*3 + 1 = 2972 (even -> sense ends at 0).
// ---------------------------------------------------------------------------
__global__ void __launch_bounds__(NTHR, 1)
ode_persistent(const float* __restrict__ z0, const float* __restrict__ tv,
               const float* __restrict__ b1, const float* __restrict__ b2,
               const float* __restrict__ b3,
               float* __restrict__ zs, float* __restrict__ h1,
               float* __restrict__ h2, float* __restrict__ za,
               float* __restrict__ zb) {
    extern __shared__ __half2 sm[];
    const uint32_t smb = smem_u32(sm);
    __shared__ unsigned s_sense;
    if (threadIdx.x == 0) s_sense = 0u;

    const int bx  = blockIdx.x;
    const int grp = bx >> 3;           // 0..15
    const int l   = bx & 7;            // 0..7

    // zs[0] rows for this group: CTA copies its 16 rows
    {
        const int rowBase = grp * 128 + l * 16;
        const float4* src = (const float4*)z0 + (size_t)rowBase * (LAT / 4);
        float4*       dst = (float4*)zs + (size_t)rowBase * (LAT / 4);
        for (int i = threadIdx.x; i < 16 * (LAT / 4); i += NTHR)
            dst[i] = __ldcg(src + i);
    }
    group_sync(&s_sense, grp);                              // barrier 1

    const int mB1 = grp * 128,                 nB1 = l * 128;       // G1/G2
    const int mB3 = grp * 128 + (l >> 2) * 64, nB3 = (l & 3) * 64;  // G3
    const size_t BL = (size_t)BATCH * LAT;

    for (int it = 0; it < TSTEPS - 1; ++it) {
        const float hstep = (__ldg(tv + it + 1) - __ldg(tv + it)) * (1.0f / NSUB);
        for (int s = 0; s < NSUB; s++) {
            const float* zin  = (s == 0)        ? zs + (size_t)it * BL
                                                : ((s & 1) ? za : zb);
            float*       zout = (s == NSUB - 1) ? zs + (size_t)(it + 1) * BL
                                                : ((s & 1) ? zb : za);
            // h1 = elu(z @ w1.T + b1)   [rows of group, K=256]
            tile_mma<128, 128, MODE_ELU>(zin, g_w1h, g_w1l, b1, nullptr, h1,
                                         HID, LAT, 0.f, mB1, nB1, sm, smb);
            group_sync(&s_sense, grp);
            // h2 = elu(h1 @ w2.T + b2)  [K=1024]
            tile_mma<128, 128, MODE_ELU>(h1, g_w2h, g_w2l, b2, nullptr, h2,
                                         HID, HID, 0.f, mB1, nB1, sm, smb);
            group_sync(&s_sense, grp);
            // zout = zin + h*(h2 @ w3.T + b3)  [K=1024]
            tile_mma<64, 64, MODE_EULER>(h2, g_w3h, g_w3l, b3, zin, zout,
                                         LAT, HID, hstep, mB3, nB3, sm, smb);
            group_sync(&s_sense, grp);
        }
    }
    group_sync(&s_sense, grp);   // pad -> even count (2972)
}

// ---------------------------------------------------------------------------
// Folded decoder: out = zs @ Md.T + cd   (M=204800, N=512, K=256)
// ---------------------------------------------------------------------------
__global__ void __launch_bounds__(NTHR, 1)
decoder_gemm(const float* __restrict__ zs, const float* __restrict__ cd,
             float* __restrict__ out) {
    extern __shared__ __half2 sm[];
    const uint32_t smb = smem_u32(sm);
    tile_mma<128, 128, MODE_PLAIN>(zs, g_Mdh, g_Mdl, cd, nullptr, out,
                                   OUTD, LAT, 0.f,
                                   blockIdx.y * 128, blockIdx.x * 128, sm, smb);
}

// ---------------------------------------------------------------------------
// Prep: decoder fold + fp16 hi/lo weight splits (tiny, once per launch)
// ---------------------------------------------------------------------------
__global__ void combine_kernel(const float* __restrict__ h2o_w,
                               const float* __restrict__ l2h_w,
                               float* __restrict__ Md) {
    __shared__ float sW[16][17];
    __shared__ float sL[16][17];
    const int o = blockIdx.y * 16 + threadIdx.y;
    const int l = blockIdx.x * 16 + threadIdx.x;
    float acc = 0.0f;
    for (int h0 = 0; h0 < HID; h0 += 16) {
        sW[threadIdx.y][threadIdx.x] = h2o_w[(size_t)o * HID + h0 + threadIdx.x];
        sL[threadIdx.y][threadIdx.x] = l2h_w[(size_t)(h0 + threadIdx.y) * LAT + l];
        __syncthreads();
#pragma unroll
        for (int kk = 0; kk < 16; kk++) acc += sW[threadIdx.y][kk] * sL[kk][threadIdx.x];
        __syncthreads();
    }
    Md[(size_t)o * LAT + l] = acc;
}

__global__ void cvec_kernel(const float* __restrict__ h2o_w,
                            const float* __restrict__ l2h_b,
                            const float* __restrict__ h2o_b,
                            float* __restrict__ cd) {
    const int o = blockIdx.x * blockDim.x + threadIdx.x;
    if (o < OUTD) {
        float a = h2o_b[o];
        for (int h = 0; h < HID; h++) a += h2o_w[(size_t)o * HID + h] * l2h_b[h];
        cd[o] = a;
    }
}

__global__ void split_kernel(const float* __restrict__ w,
                             __half* __restrict__ wh, __half* __restrict__ wl, int n) {
    const int i = blockIdx.x * blockDim.x + threadIdx.x;
    if (i < n) {
        float x = w[i];
        __half hi = __float2half_rn(x);
        wh[i] = hi;
        wl[i] = __float2half_rn(x - __half2float(hi));
    }
}

// ---------------------------------------------------------------------------
// Graph nodes: combine, cvec, 4x split, persistent ODE, decoder.
// ---------------------------------------------------------------------------
extern "C" void kernel_launch(void* const* d_in, const int* in_sizes, int n_in,
                              void* d_out, int out_size) {
    const float* z0    = (const float*)d_in[0];
    const float* tv    = (const float*)d_in[1];
    const float* w1    = (const float*)d_in[2];
    const float* b1    = (const float*)d_in[3];
    const float* w2    = (const float*)d_in[4];
    const float* b2    = (const float*)d_in[5];
    const float* w3    = (const float*)d_in[6];
    const float* b3    = (const float*)d_in[7];
    const float* l2h_w = (const float*)d_in[8];
    const float* l2h_b = (const float*)d_in[9];
    const float* h2o_w = (const float*)d_in[10];
    const float* h2o_b = (const float*)d_in[11];
    float* out = (float*)d_out;

    float *zs, *h1, *h2, *za, *zb, *Md, *cd;
    __half *w1h, *w1l, *w2h, *w2l, *w3h, *w3l, *Mdh, *Mdl;
    cudaGetSymbolAddress((void**)&zs, g_zs);
    cudaGetSymbolAddress((void**)&h1, g_h1);
    cudaGetSymbolAddress((void**)&h2, g_h2);
    cudaGetSymbolAddress((void**)&za, g_za);
    cudaGetSymbolAddress((void**)&zb, g_zb);
    cudaGetSymbolAddress((void**)&Md, g_Md);
    cudaGetSymbolAddress((void**)&cd, g_cd);
    cudaGetSymbolAddress((void**)&w1h, g_w1h);
    cudaGetSymbolAddress((void**)&w1l, g_w1l);
    cudaGetSymbolAddress((void**)&w2h, g_w2h);
    cudaGetSymbolAddress((void**)&w2l, g_w2l);
    cudaGetSymbolAddress((void**)&w3h, g_w3h);
    cudaGetSymbolAddress((void**)&w3l, g_w3l);
    cudaGetSymbolAddress((void**)&Mdh, g_Mdh);
    cudaGetSymbolAddress((void**)&Mdl, g_Mdl);

    static bool attr_done = false;
    if (!attr_done) {
        cudaFuncSetAttribute(ode_persistent,
                             cudaFuncAttributeMaxDynamicSharedMemorySize, SMEM_BYTES);
        cudaFuncSetAttribute(decoder_gemm,
                             cudaFuncAttributeMaxDynamicSharedMemorySize, SMEM_BYTES);
        attr_done = true;
    }

    // prep: decoder fold + weight splits
    combine_kernel<<<dim3(LAT / 16, OUTD / 16), dim3(16, 16)>>>(h2o_w, l2h_w, Md);
    cvec_kernel<<<2, 256>>>(h2o_w, l2h_b, h2o_b, cd);
    split_kernel<<<(HID * LAT + 255) / 256, 256>>>(w1, w1h, w1l, HID * LAT);
    split_kernel<<<(HID * HID + 255) / 256, 256>>>(w2, w2h, w2l, HID * HID);
    split_kernel<<<(LAT * HID + 255) / 256, 256>>>(w3, w3h, w3l, LAT * HID);
    split_kernel<<<(OUTD * LAT + 255) / 256, 256>>>(Md, Mdh, Mdl, OUTD * LAT);

    ode_persistent<<<NCTA, NTHR, SMEM_BYTES>>>(z0, tv, b1, b2, b3,
                                               zs, h1, h2, za, zb);

    decoder_gemm<<<dim3(OUTD / 128, TSTEPS * BATCH / 128), NTHR, SMEM_BYTES>>>(zs, cd, out);
}

// round 12
// speedup vs baseline: 1.0677x; 1.0528x over previous
#include <cuda_runtime.h>
#include <cuda_fp16.h>
#include <math.h>
#include <cstdint>

// Problem constants
#define BATCH   2048
#define LAT     256
#define HID     1024
#define OUTD    512
#define TSTEPS  100
#define NSUB    10
#define NCTA    128
#define NTHR    256
#define NGRP    16          // independent batch groups
#define GSZ     8           // CTAs per group

enum { MODE_ELU = 0, MODE_EULER = 1, MODE_PLAIN = 2 };

// ---------------------------------------------------------------------------
// Device scratch (no cudaMalloc allowed)
// ---------------------------------------------------------------------------
__device__ __align__(256) float g_zs[(size_t)TSTEPS * BATCH * LAT];
__device__ __align__(256) float g_za[(size_t)BATCH * LAT];
__device__ __align__(256) float g_zb[(size_t)BATCH * LAT];
__device__ __align__(256) float g_Md[(size_t)OUTD * LAT];
__device__ __align__(256) float g_cd[OUTD];

// Activations stored PRE-SPLIT as fp16 hi/lo (bit-identical to consumer-side split)
__device__ __align__(256) __half g_h1h[(size_t)BATCH * HID], g_h1l[(size_t)BATCH * HID];
__device__ __align__(256) __half g_h2h[(size_t)BATCH * HID], g_h2l[(size_t)BATCH * HID];

// Pre-split weights: fp16 hi/lo (hi = rn(x), lo = rn(x - hi))
__device__ __align__(256) __half g_w1h[(size_t)HID * LAT],  g_w1l[(size_t)HID * LAT];
__device__ __align__(256) __half g_w2h[(size_t)HID * HID],  g_w2l[(size_t)HID * HID];
__device__ __align__(256) __half g_w3h[(size_t)LAT * HID],  g_w3l[(size_t)LAT * HID];
__device__ __align__(256) __half g_Mdh[(size_t)OUTD * LAT], g_Mdl[(size_t)OUTD * LAT];

// Per-group barrier state: one 128B line per group. Returns to 0 every launch.
__device__ __align__(256) unsigned g_gcnt[NGRP * 32];
__device__ __align__(256) unsigned g_gsense[NGRP * 32];

// Smem: 2 buffers x 4 tiles (Ah,Al,Bh,Bl); tile = 128 rows x 36 half2
#define SA       36                    // half2 per row
#define TILE_H   (128 * SA)            // half2 per tile
#define BUF_H    (4 * TILE_H)          // half2 per buffer
#define TILE_B   (TILE_H * 4)          // bytes per tile
#define SMEM_BYTES (2 * BUF_H * 4)     // 147456 B

// ---------------------------------------------------------------------------
// Helpers
// ---------------------------------------------------------------------------
__device__ __forceinline__ uint32_t smem_u32(const void* p) {
    uint32_t a;
    asm("{ .reg .u64 t; cvta.to.shared.u64 t, %1; cvt.u32.u64 %0, t; }" : "=r"(a) : "l"(p));
    return a;
}

__device__ __forceinline__ void cp16(uint32_t dst, const void* src) {
    asm volatile("cp.async.cg.shared.global [%0], [%1], 16;" :: "r"(dst), "l"(src));
}
#define CP_COMMIT() asm volatile("cp.async.commit_group;" ::: "memory")
#define CP_WAIT0()  asm volatile("cp.async.wait_group 0;" ::: "memory")

// D += A*B (m16n8k16 fp16 inputs, fp32 accumulate)
__device__ __forceinline__ void mma16(float (&d)[4],
                                      uint32_t a0, uint32_t a1, uint32_t a2, uint32_t a3,
                                      uint32_t b0, uint32_t b1) {
    asm volatile(
        "mma.sync.aligned.m16n8k16.row.col.f32.f16.f16.f32 "
        "{%0,%1,%2,%3}, {%4,%5,%6,%7}, {%8,%9}, {%0,%1,%2,%3};"
        : "+f"(d[0]), "+f"(d[1]), "+f"(d[2]), "+f"(d[3])
        : "r"(a0), "r"(a1), "r"(a2), "r"(a3), "r"(b0), "r"(b1));
}

// split 2 floats into hi/lo packed half2 bit patterns (x -> low 16 bits)
__device__ __forceinline__ void split2(float x, float y, uint32_t& hi, uint32_t& lo) {
    __half hx = __float2half_rn(x), hy = __float2half_rn(y);
    __half lx = __float2half_rn(x - __half2float(hx));
    __half ly = __float2half_rn(y - __half2float(hy));
    hi = (uint32_t)__half_as_ushort(hx) | ((uint32_t)__half_as_ushort(hy) << 16);
    lo = (uint32_t)__half_as_ushort(lx) | ((uint32_t)__half_as_ushort(ly) << 16);
}

// ---------------------------------------------------------------------------
// Group barrier: 8 arrivals, release/acquire at gpu scope, per-group lines.
// ---------------------------------------------------------------------------
__device__ __forceinline__ void group_sync(unsigned* s_sense, int grp) {
    __syncthreads();
    if (threadIdx.x == 0) {
        unsigned* cnt = &g_gcnt[grp * 32];
        unsigned* sen = &g_gsense[grp * 32];
        unsigned my = *s_sense ^ 1u;
        *s_sense = my;
        unsigned old;
        asm volatile("atom.release.gpu.global.add.u32 %0, [%1], %2;"
                     : "=r"(old) : "l"(cnt), "r"(1u) : "memory");
        if (old == GSZ - 1u) {
            asm volatile("st.relaxed.gpu.global.u32 [%0], %1;" :: "l"(cnt), "r"(0u) : "memory");
            asm volatile("st.release.gpu.global.u32 [%0], %1;" :: "l"(sen), "r"(my) : "memory");
        } else {
            unsigned cur;
            do {
                asm volatile("ld.acquire.gpu.global.u32 %0, [%1];"
                             : "=r"(cur) : "l"(sen) : "memory");
            } while (cur != my);
        }
    }
    __syncthreads();
}

// ---------------------------------------------------------------------------
// One BM x BN output tile:  C[m,n] = epilogue( sum_k A[m,k]*W[n,k] + bias[n] )
// 3-term fp16 split (AhBh + AhBl + AlBh), fp32 register accumulators.
// AF32=true : A is fp32, split on the fly (LDG->split->STS).
// AF32=false: A is pre-split fp16 (Ah32/Al32 ignored; Ahg/Alg streamed via
//             cp.async like B -> no register staging, deep async prefetch).
// MODE_ELU writes pre-split fp16 hi/lo outputs (Ch/Cl); others write fp32 C.
// 256 threads = 8 warps (2x4). K chunks of 32. Double-buffered smem.
// ---------------------------------------------------------------------------
template <int BM, int BN, int MODE, bool AF32>
__device__ __forceinline__ void tile_mma(
    const float* __restrict__ A32,
    const __half* __restrict__ Ahg, const __half* __restrict__ Alg,
    const __half* __restrict__ Wh, const __half* __restrict__ Wl,
    const float* __restrict__ bias, const float* __restrict__ Zp,
    float* __restrict__ C, __half* __restrict__ Ch, __half* __restrict__ Cl,
    int N, int K, float h, int mB, int nB, __half2* sm, uint32_t smb) {

    constexpr int MT = BM / 32;        // mma tiles per warp (M): 4 or 2
    constexpr int NT = BN / 32;        // mma tiles per warp (N): 4 or 2
    constexpr int WM = MT * 16;
    constexpr int WN = NT * 8;
    constexpr int AG = BM * 4 / NTHR;  // A 8-float groups per thread (fp32 path)
    constexpr int AGC = BM / 64;       // A cp16 per thread per array (fp16 path)
    constexpr int BG = BN * 4 / NTHR;  // B cp16 per thread per array

    const int tid  = threadIdx.x;
    const int lane = tid & 31;
    const int warp = tid >> 5;
    const int wmi  = warp >> 2;        // 0..1
    const int wni  = warp & 3;         // 0..3
    const int nTc  = K >> 5;

    float4 ra[AF32 ? AG : 1][2];
    float acc[MT][NT][4];
#pragma unroll
    for (int i = 0; i < MT; i++)
#pragma unroll
        for (int j = 0; j < NT; j++)
#pragma unroll
            for (int c = 0; c < 4; c++) acc[i][j][c] = 0.0f;

    auto ldgA = [&](int t) {
#pragma unroll
        for (int i = 0; i < AG; i++) {
            int idx = tid + i * NTHR, row = idx >> 2, g = idx & 3;
            const float* p = A32 + (size_t)(mB + row) * K + t * 32 + g * 8;
            ra[i][0] = __ldcg((const float4*)p);
            ra[i][1] = __ldcg((const float4*)(p + 4));
        }
    };
    auto stsA = [&](int b) {
        __half2* sAh = sm + b * BUF_H;
        __half2* sAl = sAh + TILE_H;
#pragma unroll
        for (int i = 0; i < AG; i++) {
            int idx = tid + i * NTHR, row = idx >> 2, g = idx & 3;
            uint4 hi, lo;
            split2(ra[i][0].x, ra[i][0].y, hi.x, lo.x);
            split2(ra[i][0].z, ra[i][0].w, hi.y, lo.y);
            split2(ra[i][1].x, ra[i][1].y, hi.z, lo.z);
            split2(ra[i][1].z, ra[i][1].w, hi.w, lo.w);
            const int p = row * SA + g * 4;
            *(uint4*)(sAh + p) = hi;
            *(uint4*)(sAl + p) = lo;
        }
    };
    auto cpA = [&](int t, int b) {
        const uint32_t base = smb + (uint32_t)b * (BUF_H * 4);
#pragma unroll
        for (int i = 0; i < AGC; i++) {
            int idx = tid + i * NTHR, row = idx >> 2, g = idx & 3;
            const size_t o = (size_t)(mB + row) * K + t * 32 + g * 8;
            const uint32_t d = base + (uint32_t)(row * SA + g * 4) * 4;
            cp16(d, Ahg + o);
            cp16(d + TILE_B, Alg + o);
        }
    };
    auto cpB = [&](int t, int b) {
        const uint32_t base = smb + (uint32_t)b * (BUF_H * 4) + 2 * TILE_B;
#pragma unroll
        for (int i = 0; i < BG; i++) {
            int idx = tid + i * NTHR, row = idx >> 2, c = idx & 3;
            const size_t o = (size_t)(nB + row) * K + t * 32 + c * 8;
            const uint32_t d = base + (uint32_t)(row * SA + c * 4) * 4;
            cp16(d, Wh + o);
            cp16(d + TILE_B, Wl + o);
        }
    };

    // prologue: fill buffer 0
    if (AF32) ldgA(0); else cpA(0, 0);
    cpB(0, 0);
    CP_COMMIT();
    if (AF32) stsA(0);
    CP_WAIT0();
    __syncthreads();

    const int rA = wmi * WM + (lane >> 2);
    const int rB = wni * WN + (lane >> 2);
    const int cK = lane & 3;           // half2 index within 8-half2 k16 block

    for (int t = 0; t < nTc; ++t) {
        const int cur = t & 1, nxt = cur ^ 1;
        if (t + 1 < nTc) {
            if (AF32) ldgA(t + 1); else cpA(t + 1, nxt);
            cpB(t + 1, nxt);
            CP_COMMIT();
        }

        const uint32_t* sAh = (const uint32_t*)(sm + cur * BUF_H);
        const uint32_t* sAl = sAh + TILE_H;
        const uint32_t* sBh = sAl + TILE_H;
        const uint32_t* sBl = sBh + TILE_H;

#pragma unroll
        for (int blk = 0; blk < 2; blk++) {          // two k16 blocks per chunk
            const int kb = blk * 8 + cK;
            uint32_t ah[MT][4], al[MT][4], bh[NT][2], bl[NT][2];
#pragma unroll
            for (int i = 0; i < MT; i++) {
                const int r0 = (rA + i * 16) * SA, r1 = r0 + 8 * SA;
                ah[i][0] = sAh[r0 + kb];
                ah[i][1] = sAh[r1 + kb];
                ah[i][2] = sAh[r0 + kb + 4];
                ah[i][3] = sAh[r1 + kb + 4];
                al[i][0] = sAl[r0 + kb];
                al[i][1] = sAl[r1 + kb];
                al[i][2] = sAl[r0 + kb + 4];
                al[i][3] = sAl[r1 + kb + 4];
            }
#pragma unroll
            for (int j = 0; j < NT; j++) {
                const int rn = (rB + j * 8) * SA;
                bh[j][0] = sBh[rn + kb];
                bh[j][1] = sBh[rn + kb + 4];
                bl[j][0] = sBl[rn + kb];
                bl[j][1] = sBl[rn + kb + 4];
            }
#pragma unroll
            for (int i = 0; i < MT; i++)
#pragma unroll
                for (int j = 0; j < NT; j++) {
                    mma16(acc[i][j], ah[i][0], ah[i][1], ah[i][2], ah[i][3], bh[j][0], bh[j][1]);
                    mma16(acc[i][j], ah[i][0], ah[i][1], ah[i][2], ah[i][3], bl[j][0], bl[j][1]);
                    mma16(acc[i][j], al[i][0], al[i][1], al[i][2], al[i][3], bh[j][0], bh[j][1]);
                }
        }

        if (t + 1 < nTc) {
            if (AF32) stsA(nxt);
            CP_WAIT0();
            __syncthreads();
        }
    }

    // ---- epilogue ----
#pragma unroll
    for (int i = 0; i < MT; i++) {
        const int gm0 = mB + wmi * WM + i * 16 + (lane >> 2);
#pragma unroll
        for (int j = 0; j < NT; j++) {
            const int gn = nB + wni * WN + j * 8 + (lane & 3) * 2;
            const float bi0 = __ldg(bias + gn), bi1 = __ldg(bias + gn + 1);
            float x0 = acc[i][j][0] + bi0, x1 = acc[i][j][1] + bi1;
            float x2 = acc[i][j][2] + bi0, x3 = acc[i][j][3] + bi1;
            const size_t g0 = (size_t)gm0 * N + gn;
            const size_t g1 = (size_t)(gm0 + 8) * N + gn;
            if (MODE == MODE_ELU) {
                x0 = x0 > 0.0f ? x0 : expm1f(x0);
                x1 = x1 > 0.0f ? x1 : expm1f(x1);
                x2 = x2 > 0.0f ? x2 : expm1f(x2);
                x3 = x3 > 0.0f ? x3 : expm1f(x3);
                // write PRE-SPLIT hi/lo (bit-identical to consumer-side split)
                uint32_t h01, l01, h23, l23;
                split2(x0, x1, h01, l01);
                split2(x2, x3, h23, l23);
                *(uint32_t*)(Ch + g0) = h01;
                *(uint32_t*)(Cl + g0) = l01;
                *(uint32_t*)(Ch + g1) = h23;
                *(uint32_t*)(Cl + g1) = l23;
            } else {
                if (MODE == MODE_EULER) {
                    float2 z0v = __ldcg((const float2*)(Zp + g0));
                    float2 z1v = __ldcg((const float2*)(Zp + g1));
                    x0 = z0v.x + h * x0; x1 = z0v.y + h * x1;
                    x2 = z1v.x + h * x2; x3 = z1v.y + h * x3;
                }
                *(float2*)(C + g0) = make_float2(x0, x1);
                *(float2*)(C + g1) = make_float2(x2, x3);
            }
        }
    }
}

// ---------------------------------------------------------------------------
// Persistent ODE integrator: 16 groups of 8 CTAs; group g owns rows
// [128g, 128g+128). Per-group barriers: 1 + 2970 + 1 = 2972 (even).
// ---------------------------------------------------------------------------
__global__ void __launch_bounds__(NTHR, 1)
ode_persistent(const float* __restrict__ z0, const float* __restrict__ tv,
               const float* __restrict__ b1, const float* __restrict__ b2,
               const float* __restrict__ b3,
               float* __restrict__ zs, float* __restrict__ za,
               float* __restrict__ zb) {
    extern __shared__ __half2 sm[];
    const uint32_t smb = smem_u32(sm);
    __shared__ unsigned s_sense;
    if (threadIdx.x == 0) s_sense = 0u;

    const int bx  = blockIdx.x;
    const int grp = bx >> 3;           // 0..15
    const int l   = bx & 7;            // 0..7

    // zs[0] rows for this group
    {
        const int rowBase = grp * 128 + l * 16;
        const float4* src = (const float4*)z0 + (size_t)rowBase * (LAT / 4);
        float4*       dst = (float4*)zs + (size_t)rowBase * (LAT / 4);
        for (int i = threadIdx.x; i < 16 * (LAT / 4); i += NTHR)
            dst[i] = __ldcg(src + i);
    }
    group_sync(&s_sense, grp);                              // barrier 1

    const int mB1 = grp * 128,                 nB1 = l * 128;       // G1/G2
    const int mB3 = grp * 128 + (l >> 2) * 64, nB3 = (l & 3) * 64;  // G3
    const size_t BL = (size_t)BATCH * LAT;

    for (int it = 0; it < TSTEPS - 1; ++it) {
        const float hstep = (__ldg(tv + it + 1) - __ldg(tv + it)) * (1.0f / NSUB);
        for (int s = 0; s < NSUB; s++) {
            const float* zin  = (s == 0)        ? zs + (size_t)it * BL
                                                : ((s & 1) ? za : zb);
            float*       zout = (s == NSUB - 1) ? zs + (size_t)(it + 1) * BL
                                                : ((s & 1) ? zb : za);
            // h1 = elu(z @ w1.T + b1)   [K=256]  A=fp32 z, out=pre-split h1
            tile_mma<128, 128, MODE_ELU, true>(
                zin, nullptr, nullptr, g_w1h, g_w1l, b1, nullptr,
                nullptr, g_h1h, g_h1l, HID, LAT, 0.f, mB1, nB1, sm, smb);
            group_sync(&s_sense, grp);
            // h2 = elu(h1 @ w2.T + b2)  [K=1024] A=pre-split h1, out=pre-split h2
            tile_mma<128, 128, MODE_ELU, false>(
                nullptr, g_h1h, g_h1l, g_w2h, g_w2l, b2, nullptr,
                nullptr, g_h2h, g_h2l, HID, HID, 0.f, mB1, nB1, sm, smb);
            group_sync(&s_sense, grp);
            // zout = zin + h*(h2 @ w3.T + b3)  [K=1024] A=pre-split h2
            tile_mma<64, 64, MODE_EULER, false>(
                nullptr, g_h2h, g_h2l, g_w3h, g_w3l, b3, zin,
                zout, nullptr, nullptr, LAT, HID, hstep, mB3, nB3, sm, smb);
            group_sync(&s_sense, grp);
        }
    }
    group_sync(&s_sense, grp);   // pad -> even count (2972)
}

// ---------------------------------------------------------------------------
// Folded decoder: out = zs @ Md.T + cd   (M=204800, N=512, K=256)
// ---------------------------------------------------------------------------
__global__ void __launch_bounds__(NTHR, 1)
decoder_gemm(const float* __restrict__ zs, const float* __restrict__ cd,
             float* __restrict__ out) {
    extern __shared__ __half2 sm[];
    const uint32_t smb = smem_u32(sm);
    tile_mma<128, 128, MODE_PLAIN, true>(
        zs, nullptr, nullptr, g_Mdh, g_Mdl, cd, nullptr,
        out, nullptr, nullptr, OUTD, LAT, 0.f,
        blockIdx.y * 128, blockIdx.x * 128, sm, smb);
}

// ---------------------------------------------------------------------------
// Prep kernels
// ---------------------------------------------------------------------------
__global__ void combine_kernel(const float* __restrict__ h2o_w,
                               const float* __restrict__ l2h_w,
                               float* __restrict__ Md) {
    __shared__ float sW[16][17];
    __shared__ float sL[16][17];
    const int o = blockIdx.y * 16 + threadIdx.y;
    const int l = blockIdx.x * 16 + threadIdx.x;
    float acc = 0.0f;
    for (int h0 = 0; h0 < HID; h0 += 16) {
        sW[threadIdx.y][threadIdx.x] = h2o_w[(size_t)o * HID + h0 + threadIdx.x];
        sL[threadIdx.y][threadIdx.x] = l2h_w[(size_t)(h0 + threadIdx.y) * LAT + l];
        __syncthreads();
#pragma unroll
        for (int kk = 0; kk < 16; kk++) acc += sW[threadIdx.y][kk] * sL[kk][threadIdx.x];
        __syncthreads();
    }
    Md[(size_t)o * LAT + l] = acc;
}

__global__ void cvec_kernel(const float* __restrict__ h2o_w,
                            const float* __restrict__ l2h_b,
                            const float* __restrict__ h2o_b,
                            float* __restrict__ cd) {
    const int o = blockIdx.x * blockDim.x + threadIdx.x;
    if (o < OUTD) {
        float a = h2o_b[o];
        for (int h = 0; h < HID; h++) a += h2o_w[(size_t)o * HID + h] * l2h_b[h];
        cd[o] = a;
    }
}

__global__ void split_kernel(const float* __restrict__ w,
                             __half* __restrict__ wh, __half* __restrict__ wl, int n) {
    const int i = blockIdx.x * blockDim.x + threadIdx.x;
    if (i < n) {
        float x = w[i];
        __half hi = __float2half_rn(x);
        wh[i] = hi;
        wl[i] = __float2half_rn(x - __half2float(hi));
    }
}

// ---------------------------------------------------------------------------
// Launch order matters for ncu (-s 5 -c 1): #5 must be ode_persistent.
//   0 combine, 1 cvec, 2 split(w1), 3 split(w2), 4 split(w3),
//   5 ODE, 6 split(Md), 7 decoder.
// (Md split only feeds the decoder, so it can legally run after the ODE.)
// ---------------------------------------------------------------------------
extern "C" void kernel_launch(void* const* d_in, const int* in_sizes, int n_in,
                              void* d_out, int out_size) {
    const float* z0    = (const float*)d_in[0];
    const float* tv    = (const float*)d_in[1];
    const float* w1    = (const float*)d_in[2];
    const float* b1    = (const float*)d_in[3];
    const float* w2    = (const float*)d_in[4];
    const float* b2    = (const float*)d_in[5];
    const float* w3    = (const float*)d_in[6];
    const float* b3    = (const float*)d_in[7];
    const float* l2h_w = (const float*)d_in[8];
    const float* l2h_b = (const float*)d_in[9];
    const float* h2o_w = (const float*)d_in[10];
    const float* h2o_b = (const float*)d_in[11];
    float* out = (float*)d_out;

    float *zs, *za, *zb, *Md, *cd;
    __half *w1h, *w1l, *w2h, *w2l, *w3h, *w3l, *Mdh, *Mdl;
    cudaGetSymbolAddress((void**)&zs, g_zs);
    cudaGetSymbolAddress((void**)&za, g_za);
    cudaGetSymbolAddress((void**)&zb, g_zb);
    cudaGetSymbolAddress((void**)&Md, g_Md);
    cudaGetSymbolAddress((void**)&cd, g_cd);
    cudaGetSymbolAddress((void**)&w1h, g_w1h);
    cudaGetSymbolAddress((void**)&w1l, g_w1l);
    cudaGetSymbolAddress((void**)&w2h, g_w2h);
    cudaGetSymbolAddress((void**)&w2l, g_w2l);
    cudaGetSymbolAddress((void**)&w3h, g_w3h);
    cudaGetSymbolAddress((void**)&w3l, g_w3l);
    cudaGetSymbolAddress((void**)&Mdh, g_Mdh);
    cudaGetSymbolAddress((void**)&Mdl, g_Mdl);

    static bool attr_done = false;
    if (!attr_done) {
        cudaFuncSetAttribute(ode_persistent,
                             cudaFuncAttributeMaxDynamicSharedMemorySize, SMEM_BYTES);
        cudaFuncSetAttribute(decoder_gemm,
                             cudaFuncAttributeMaxDynamicSharedMemorySize, SMEM_BYTES);
        attr_done = true;
    }

    combine_kernel<<<dim3(LAT / 16, OUTD / 16), dim3(16, 16)>>>(h2o_w, l2h_w, Md);   // 0
    cvec_kernel<<<2, 256>>>(h2o_w, l2h_b, h2o_b, cd);                                // 1
    split_kernel<<<(HID * LAT + 255) / 256, 256>>>(w1, w1h, w1l, HID * LAT);         // 2
    split_kernel<<<(HID * HID + 255) / 256, 256>>>(w2, w2h, w2l, HID * HID);         // 3
    split_kernel<<<(LAT * HID + 255) / 256, 256>>>(w3, w3h, w3l, LAT * HID);         // 4

    ode_persistent<<<NCTA, NTHR, SMEM_BYTES>>>(z0, tv, b1, b2, b3, zs, za, zb);      // 5

    split_kernel<<<(OUTD * LAT + 255) / 256, 256>>>(Md, Mdh, Mdl, OUTD * LAT);       // 6

    decoder_gemm<<<dim3(OUTD / 128, TSTEPS * BATCH / 128), NTHR, SMEM_BYTES>>>(zs, cd, out);  // 7
}